// round 2
// baseline (speedup 1.0000x reference)
#include <cuda_runtime.h>
#include <cuda_bf16.h>
#include <math.h>

// ---------------- problem constants ----------------
#define EPSBN 1e-3f
static const int NS_[3] = {40000, 20000, 8000};
static const int HS_[3] = {496, 248, 124};
static const int WS_[3] = {432, 216, 108};
#define BATCH 4
#define TPTS 32

#define HW0 (496*432)
#define HW1 (248*216)
#define HW2 (124*108)

// ---------------- device scratch (static, no runtime alloc) ----------------
__device__ float g_w1f[3*9*64];
__device__ float g_b1f[3*64];
__device__ float g_w2f[3*128*64];
__device__ float g_b2f[3*64];
__device__ float g_fwf[2*128*9*64];   // [layer][ic][k][oc] folded conv weights
__device__ float g_fbf[2*64];

__device__ float g_vf[40000*64];
__device__ int   g_win[BATCH*HW0];

__device__ float g_cat0[(size_t)BATCH*128*HW0];
__device__ float g_cat1[(size_t)BATCH*128*HW1];
__device__ float g_sf2 [(size_t)BATCH*64*HW2];
__device__ float g_f1  [(size_t)BATCH*64*HW1];

// ---------------- weight folding ----------------
__global__ void fold_kernel(const float* __restrict__ w1, const float* __restrict__ g1,
                            const float* __restrict__ b1, const float* __restrict__ rm1,
                            const float* __restrict__ rv1,
                            const float* __restrict__ w2, const float* __restrict__ g2,
                            const float* __restrict__ b2, const float* __restrict__ rm2,
                            const float* __restrict__ rv2,
                            const float* __restrict__ fw, const float* __restrict__ fg,
                            const float* __restrict__ fb, const float* __restrict__ fm,
                            const float* __restrict__ fv) {
    int idx = blockIdx.x * blockDim.x + threadIdx.x;
    if (idx < 1728) {
        int s = idx / 576; int d = idx % 64;
        float sc = g1[s*64+d] * rsqrtf(rv1[s*64+d] + EPSBN);
        g_w1f[idx] = w1[idx] * sc;
    }
    if (idx < 24576) {
        int s = idx / 8192; int d = idx % 64;
        float sc = g2[s*64+d] * rsqrtf(rv2[s*64+d] + EPSBN);
        g_w2f[idx] = w2[idx] * sc;
    }
    if (idx < 147456) {
        int l = idx / 73728; int r = idx % 73728;
        int ic = r / 576; int k = (r % 576) / 64; int oc = r % 64;
        float sc = fg[l*64+oc] * rsqrtf(fv[l*64+oc] + EPSBN);
        g_fwf[idx] = fw[(((size_t)(l*64+oc)*128 + ic)*9) + k] * sc;
    }
    if (idx < 192) {
        float sc1 = g1[idx] * rsqrtf(rv1[idx] + EPSBN);
        g_b1f[idx] = b1[idx] - rm1[idx] * sc1;
        float sc2 = g2[idx] * rsqrtf(rv2[idx] + EPSBN);
        g_b2f[idx] = b2[idx] - rm2[idx] * sc2;
    }
    if (idx < 128) {
        float sc = fg[idx] * rsqrtf(fv[idx] + EPSBN);
        g_fbf[idx] = fb[idx] - fm[idx] * sc;
    }
}

// ---------------- VFE: one block (64 threads) per voxel ----------------
__global__ void vfe_kernel(const float* __restrict__ voxels, const int* __restrict__ numpts,
                           const float* __restrict__ w1f, const float* __restrict__ b1f,
                           const float* __restrict__ w2f, const float* __restrict__ b2f,
                           float* __restrict__ vfout, int N) {
    __shared__ float w1s[576];
    __shared__ float w2s[8192];
    __shared__ float b1sm[64];
    __shared__ float b2sm[64];
    __shared__ float feat[288];    // [32][9]
    __shared__ float h1s[2048];    // [32][64]
    __shared__ float gmaxs[64];
    __shared__ float mean3[3];

    int v = blockIdx.x;
    if (v >= N) return;
    int t = threadIdx.x;  // 0..63

    for (int i = t; i < 576; i += 64)  w1s[i] = w1f[i];
    for (int i = t; i < 8192; i += 64) w2s[i] = w2f[i];
    if (t < 64) { b1sm[t] = b1f[t]; b2sm[t] = b2f[t]; }

    int np = numpts[v];

    float4 p = make_float4(0.f, 0.f, 0.f, 0.f);
    if (t < 32) {
        p = ((const float4*)voxels)[(size_t)v * TPTS + t];
        float sx = p.x, sy = p.y, sz = p.z;
        #pragma unroll
        for (int o = 16; o > 0; o >>= 1) {
            sx += __shfl_down_sync(0xffffffffu, sx, o);
            sy += __shfl_down_sync(0xffffffffu, sy, o);
            sz += __shfl_down_sync(0xffffffffu, sz, o);
        }
        if (t == 0) {
            float inv = 1.0f / (float)np;
            mean3[0] = sx * inv; mean3[1] = sy * inv; mean3[2] = sz * inv;
        }
    }
    __syncthreads();
    if (t < 32) {
        float mx = mean3[0], my = mean3[1], mz = mean3[2];
        float* f = &feat[t * 9];
        f[0] = p.x; f[1] = p.y; f[2] = p.z; f[3] = p.w;
        f[4] = p.x - mx; f[5] = p.y - my; f[6] = p.z - mz;
        f[7] = p.x - mx; f[8] = p.y - my;
    }
    __syncthreads();

    // layer 1 over ALL 32 points (unmasked, matches reference gmax semantics)
    int c = t;
    float b1v = b1sm[c];
    float gm = -1e30f;
    for (int tt = 0; tt < TPTS; tt++) {
        float a = b1v;
        #pragma unroll
        for (int k = 0; k < 9; k++) a = fmaf(feat[tt*9+k], w1s[k*64+c], a);
        a = fmaxf(a, 0.f);
        h1s[tt*64+c] = a;
        gm = fmaxf(gm, a);
    }
    gmaxs[c] = gm;
    __syncthreads();

    // gmax contribution of layer2 (constant over points)
    float gterm = b2sm[c];
    #pragma unroll 8
    for (int j = 0; j < 64; j++) gterm = fmaf(gmaxs[j], w2s[(64+j)*64+c], gterm);

    // layer 2 over valid points only; relu+mask+max == max-chain init 0
    float vmax = 0.f;
    int tt = 0;
    for (; tt + 4 <= np; tt += 4) {
        float a0 = gterm, a1 = gterm, a2 = gterm, a3 = gterm;
        const float* h0 = &h1s[tt*64];
        #pragma unroll 8
        for (int j = 0; j < 64; j++) {
            float w = w2s[j*64+c];
            a0 = fmaf(h0[j],       w, a0);
            a1 = fmaf(h0[64+j],    w, a1);
            a2 = fmaf(h0[128+j],   w, a2);
            a3 = fmaf(h0[192+j],   w, a3);
        }
        vmax = fmaxf(vmax, fmaxf(fmaxf(a0, a1), fmaxf(a2, a3)));
    }
    for (; tt < np; tt++) {
        float a = gterm;
        #pragma unroll 8
        for (int j = 0; j < 64; j++) a = fmaf(h1s[tt*64+j], w2s[j*64+c], a);
        vmax = fmaxf(vmax, a);
    }
    vfout[(size_t)v*64 + c] = vmax;
}

// ---------------- scatter ----------------
__global__ void fill_win_kernel(int* __restrict__ p, int n) {
    int i = blockIdx.x * blockDim.x + threadIdx.x;
    if (i < n) p[i] = -1;
}

__global__ void scatter_max_kernel(const int* __restrict__ coords, int* __restrict__ win,
                                   int N, int H, int W) {
    int v = blockIdx.x * blockDim.x + threadIdx.x;
    if (v >= N) return;
    int b = coords[v*4];
    int y = min(max(coords[v*4+2], 0), H-1);
    int x = min(max(coords[v*4+3], 0), W-1);
    atomicMax(&win[(b*H + y)*W + x], v);
}

__global__ void scatter_write_kernel(const int* __restrict__ coords, const int* __restrict__ win,
                                     const float* __restrict__ vf, float* __restrict__ dst,
                                     int H, int W, int CC) {
    int v = blockIdx.x;
    int c = threadIdx.x;  // 64
    int b = coords[v*4];
    int y = min(max(coords[v*4+2], 0), H-1);
    int x = min(max(coords[v*4+3], 0), W-1);
    if (win[(b*H + y)*W + x] != v) return;
    dst[((size_t)(b*CC + c)*H + y)*W + x] = vf[(size_t)v*64 + c];
}

// ---------------- zeroing ----------------
__global__ void zero_ch_kernel(float* __restrict__ base, size_t perBatchStride, size_t count, int nb) {
    size_t total = count * (size_t)nb;
    for (size_t i = (size_t)blockIdx.x * blockDim.x + threadIdx.x; i < total;
         i += (size_t)gridDim.x * blockDim.x) {
        size_t b = i / count;
        size_t off = i % count;
        base[b * perBatchStride + off] = 0.f;
    }
}

// ---------------- bilinear 2x upsample (jax half-pixel + edge renorm == clamp) ----------------
__global__ void upsample2x_kernel(const float* __restrict__ in, float* __restrict__ outbase,
                                  int Hi, int Wi, int Ho, int Wo, int outC, int chOff) {
    size_t total = (size_t)BATCH * 64 * Ho * Wo;
    for (size_t i = (size_t)blockIdx.x * blockDim.x + threadIdx.x; i < total;
         i += (size_t)gridDim.x * blockDim.x) {
        int x = (int)(i % Wo);
        int y = (int)((i / Wo) % Ho);
        int c = (int)((i / ((size_t)Wo * Ho)) % 64);
        int b = (int)(i / ((size_t)Wo * Ho * 64));
        float fy = fminf(fmaxf(y * 0.5f - 0.25f, 0.f), (float)(Hi - 1));
        float fx = fminf(fmaxf(x * 0.5f - 0.25f, 0.f), (float)(Wi - 1));
        int y0 = (int)fy; int x0 = (int)fx;
        float wy = fy - y0, wx = fx - x0;
        int y1 = min(y0 + 1, Hi - 1), x1 = min(x0 + 1, Wi - 1);
        const float* src = in + ((size_t)(b*64 + c) * Hi) * Wi;
        float v00 = src[(size_t)y0*Wi + x0], v01 = src[(size_t)y0*Wi + x1];
        float v10 = src[(size_t)y1*Wi + x0], v11 = src[(size_t)y1*Wi + x1];
        float val = (1.f-wy)*((1.f-wx)*v00 + wx*v01) + wy*((1.f-wx)*v10 + wx*v11);
        outbase[((size_t)(b*outC + chOff + c) * Ho + y) * Wo + x] = val;
    }
}

// ---------------- 3x3 conv 128->64 + folded BN + relu ----------------
__global__ __launch_bounds__(256, 2)
void conv3x3_kernel(const float* __restrict__ in, float* __restrict__ out,
                    int H, int W, const float* __restrict__ wfold, const float* __restrict__ bfold) {
    __shared__ float insm[8][18][18];
    __shared__ float wsm[8*9*64];

    int b = blockIdx.z;
    int ty0 = blockIdx.y * 16;
    int tx0 = blockIdx.x * 16;
    int t = threadIdx.x;
    int oc0 = (t & 15) * 4;
    int s = t >> 4;
    int sy0 = (s >> 2) * 4;
    int sx0 = (s & 3) * 4;

    float4 acc[16];
    #pragma unroll
    for (int u = 0; u < 16; u++) acc[u] = make_float4(0.f, 0.f, 0.f, 0.f);

    const float* inb = in + (size_t)b * 128 * H * W;

    for (int icb = 0; icb < 128; icb += 8) {
        __syncthreads();
        for (int i = t; i < 8*18*18; i += 256) {
            int ic = i / 324;
            int r = (i / 18) % 18;
            int cc = i % 18;
            int gy = ty0 + r - 1, gx = tx0 + cc - 1;
            float v = 0.f;
            if (gy >= 0 && gy < H && gx >= 0 && gx < W)
                v = inb[(size_t)(icb + ic) * H * W + (size_t)gy * W + gx];
            insm[ic][r][cc] = v;
        }
        const float* wsrc = wfold + (size_t)icb * 576;
        for (int i = t; i < 4608; i += 256) wsm[i] = wsrc[i];
        __syncthreads();

        for (int ic = 0; ic < 8; ic++) {
            #pragma unroll
            for (int ky = 0; ky < 3; ky++) {
                #pragma unroll
                for (int kx = 0; kx < 3; kx++) {
                    float4 w = *(const float4*)&wsm[(ic*9 + ky*3 + kx)*64 + oc0];
                    #pragma unroll
                    for (int uy = 0; uy < 4; uy++) {
                        #pragma unroll
                        for (int ux = 0; ux < 4; ux++) {
                            float iv = insm[ic][sy0+uy+ky][sx0+ux+kx];
                            float4& a = acc[uy*4+ux];
                            a.x = fmaf(w.x, iv, a.x);
                            a.y = fmaf(w.y, iv, a.y);
                            a.z = fmaf(w.z, iv, a.z);
                            a.w = fmaf(w.w, iv, a.w);
                        }
                    }
                }
            }
        }
    }

    float bias[4];
    #pragma unroll
    for (int j = 0; j < 4; j++) bias[j] = bfold[oc0 + j];
    int gx0 = tx0 + sx0;
    if (gx0 < W) {
        #pragma unroll
        for (int uy = 0; uy < 4; uy++) {
            int gy = ty0 + sy0 + uy;
            if (gy >= H) continue;
            #pragma unroll
            for (int j = 0; j < 4; j++) {
                float4 rowv;
                rowv.x = fmaxf(((const float*)&acc[uy*4+0])[j] + bias[j], 0.f);
                rowv.y = fmaxf(((const float*)&acc[uy*4+1])[j] + bias[j], 0.f);
                rowv.z = fmaxf(((const float*)&acc[uy*4+2])[j] + bias[j], 0.f);
                rowv.w = fmaxf(((const float*)&acc[uy*4+3])[j] + bias[j], 0.f);
                float* dst = out + ((size_t)(b*64 + oc0 + j) * H + gy) * W + gx0;
                *(float4*)dst = rowv;
            }
        }
    }
}

// ---------------- launch ----------------
extern "C" void kernel_launch(void* const* d_in, const int* in_sizes, int n_in,
                              void* d_out, int out_size) {
    (void)out_size;
    // Identify inputs by element count (robust to metadata ordering).
    const float* voxels[3] = {0,0,0};
    const int* numpts[3] = {0,0,0};
    const int* coordsp[3] = {0,0,0};
    const float *w1=0,*w2=0,*fw=0;
    const float* p192[8] = {0};
    const float* p128[4] = {0};
    int n192 = 0, n128 = 0;
    for (int i = 0; i < n_in; i++) {
        int sz = in_sizes[i];
        const void* p = d_in[i];
        switch (sz) {
            case 5120000: voxels[0] = (const float*)p; break;
            case 2560000: voxels[1] = (const float*)p; break;
            case 1024000: voxels[2] = (const float*)p; break;
            case 40000:   numpts[0] = (const int*)p; break;
            case 20000:   numpts[1] = (const int*)p; break;
            case 8000:    numpts[2] = (const int*)p; break;
            case 160000:  coordsp[0] = (const int*)p; break;
            case 80000:   coordsp[1] = (const int*)p; break;
            case 32000:   coordsp[2] = (const int*)p; break;
            case 1728:    w1 = (const float*)p; break;
            case 24576:   w2 = (const float*)p; break;
            case 147456:  fw = (const float*)p; break;
            case 192:     if (n192 < 8) p192[n192++] = (const float*)p; break;
            case 128:     if (n128 < 4) p128[n128++] = (const float*)p; break;
            default: break; // batch_size scalar
        }
    }
    // Relative order of equal-size params is g,b,rm,rv in both candidate orderings.
    const float *g1=p192[0], *b1=p192[1], *rm1=p192[2], *rv1=p192[3];
    const float *g2=p192[4], *b2=p192[5], *rm2=p192[6], *rv2=p192[7];
    const float *fg=p128[0], *fb=p128[1], *fm=p128[2], *fv=p128[3];

    float* cat0; cudaGetSymbolAddress((void**)&cat0, g_cat0);
    float* cat1; cudaGetSymbolAddress((void**)&cat1, g_cat1);
    float* sf2;  cudaGetSymbolAddress((void**)&sf2,  g_sf2);
    float* f1;   cudaGetSymbolAddress((void**)&f1,   g_f1);
    float* vf;   cudaGetSymbolAddress((void**)&vf,   g_vf);
    int*   win;  cudaGetSymbolAddress((void**)&win,  g_win);
    float* w1f;  cudaGetSymbolAddress((void**)&w1f,  g_w1f);
    float* b1f;  cudaGetSymbolAddress((void**)&b1f,  g_b1f);
    float* w2f;  cudaGetSymbolAddress((void**)&w2f,  g_w2f);
    float* b2f;  cudaGetSymbolAddress((void**)&b2f,  g_b2f);
    float* fwf;  cudaGetSymbolAddress((void**)&fwf,  g_fwf);
    float* fbf;  cudaGetSymbolAddress((void**)&fbf,  g_fbf);

    fold_kernel<<<576, 256>>>(w1, g1, b1, rm1, rv1, w2, g2, b2, rm2, rv2, fw, fg, fb, fm, fv);

    zero_ch_kernel<<<2048, 256>>>(cat0, (size_t)128*HW0, (size_t)64*HW0, BATCH);
    zero_ch_kernel<<<1024, 256>>>(cat1, (size_t)128*HW1, (size_t)64*HW1, BATCH);
    zero_ch_kernel<<<512, 256>>>(sf2, (size_t)BATCH*64*HW2, (size_t)BATCH*64*HW2, 1);

    float* dsts[3] = {cat0, cat1, sf2};
    int ccs[3] = {128, 128, 64};
    for (int s = 0; s < 3; s++) {
        int N = NS_[s], H = HS_[s], W = WS_[s];
        vfe_kernel<<<N, 64>>>(voxels[s], numpts[s], w1f + s*576, b1f + s*64,
                              w2f + s*8192, b2f + s*64, vf, N);
        int cells = BATCH * H * W;
        fill_win_kernel<<<(cells + 255)/256, 256>>>(win, cells);
        scatter_max_kernel<<<(N + 255)/256, 256>>>(coordsp[s], win, N, H, W);
        scatter_write_kernel<<<N, 64>>>(coordsp[s], win, vf, dsts[s], H, W, ccs[s]);
    }

    upsample2x_kernel<<<4096, 256>>>(sf2, cat1, 124, 108, 248, 216, 128, 64);

    {
        dim3 grid((216 + 15)/16, (248 + 15)/16, BATCH);
        conv3x3_kernel<<<grid, 256>>>(cat1, f1, 248, 216, fwf + 73728, fbf + 64);
    }

    upsample2x_kernel<<<8192, 256>>>(f1, cat0, 248, 216, 496, 432, 128, 64);

    {
        dim3 grid((432 + 15)/16, (496 + 15)/16, BATCH);
        conv3x3_kernel<<<grid, 256>>>(cat0, (float*)d_out, 496, 432, fwf, fbf);
    }
}